// round 4
// baseline (speedup 1.0000x reference)
#include <cuda_runtime.h>
#include <math.h>
#include <stdint.h>

// VQ-EMA inference forward:
//   z [N=32768, D=256] fp32, embed [K=8192, D=256] fp32
//   outputs (concatenated fp32): z_q_st [N*D], loss [1], perplexity [1], idx [N]
//
// argmin_k ||z - e_k||^2 == argmin_k (||e_k||^2 - 2 z.e_k)  (drop per-row ||z||^2)

#define DIM 256
#define BM  128
#define BN  128
#define DC  32
#define TPB 256

#define MAX_N 32768
#define MAX_K 8192

__device__ int    g_idx[MAX_N];
__device__ float  g_e2[MAX_K];
__device__ int    g_counts[MAX_K];
__device__ double g_losspart[MAX_N / 8];

// ---------------------------------------------------------------------------
// k_prep: ||e_k||^2 per code (warp per code), zero histogram. Re-run per launch
// (graph-capturable, no persistent state assumptions).
// ---------------------------------------------------------------------------
__global__ void k_prep(const float* __restrict__ embed, int K) {
    int code = blockIdx.x * 8 + (threadIdx.x >> 5);
    int lane = threadIdx.x & 31;
    if (code < K) {
        const float* e = embed + (size_t)code * DIM;
        float s = 0.f;
        #pragma unroll
        for (int q = 0; q < DIM / 32; q++) {
            float v = e[lane + q * 32];
            s = fmaf(v, v, s);
        }
        #pragma unroll
        for (int o = 16; o; o >>= 1) s += __shfl_xor_sync(0xFFFFFFFFu, s, o);
        if (lane == 0) { g_e2[code] = s; g_counts[code] = 0; }
    }
}

// ---------------------------------------------------------------------------
// k_argmin: fused fp32 GEMM + per-row argmin.
// Block: 128 rows x 128-code tiles, loop over all K. 256 threads, 8x8 rmem
// micro-tile (rows ty*4+{0..3} & 64+ty*4+{0..3}; codes tx*4+{0..3} & 64+...).
// Smem tiles stored transposed: [d][row] so the d-loop reads are float4.
// ---------------------------------------------------------------------------
__global__ void __launch_bounds__(TPB, 2)
k_argmin(const float* __restrict__ z, const float* __restrict__ embed,
         int N, int K) {
    __shared__ float zs[DC][BM + 4];
    __shared__ float es[DC][BN + 4];

    const int tid = threadIdx.x;
    const int tx = tid & 15;
    const int ty = tid >> 4;
    const int m0 = blockIdx.x * BM;

    const int r0 = ty * 4;
    const int r1 = 64 + ty * 4;
    const int c0 = tx * 4;
    const int c1 = 64 + tx * 4;

    float best[8];
    int   bidx[8];
    #pragma unroll
    for (int i = 0; i < 8; i++) { best[i] = INFINITY; bidx[i] = 0; }

    const int lr = tid >> 3;        // 0..31: row within a 32-row load group
    const int lc = (tid & 7) * 4;   // 0,4,...,28: starting column (float4)

    for (int ct = 0; ct < K; ct += BN) {
        float acc[8][8];
        #pragma unroll
        for (int i = 0; i < 8; i++) {
            #pragma unroll
            for (int j = 0; j < 8; j++) acc[i][j] = 0.f;
        }

        for (int dc = 0; dc < DIM; dc += DC) {
            // load + transpose z tile: zs[c][r] = z[m0+r][dc+c]
            #pragma unroll
            for (int p = 0; p < 4; p++) {
                int row = lr + p * 32;
                float4 v = *(const float4*)(z + (size_t)(m0 + row) * DIM + dc + lc);
                zs[lc + 0][row] = v.x; zs[lc + 1][row] = v.y;
                zs[lc + 2][row] = v.z; zs[lc + 3][row] = v.w;
            }
            // load + transpose embed tile: es[c][n] = embed[ct+n][dc+c]
            #pragma unroll
            for (int p = 0; p < 4; p++) {
                int row = lr + p * 32;
                float4 v = *(const float4*)(embed + (size_t)(ct + row) * DIM + dc + lc);
                es[lc + 0][row] = v.x; es[lc + 1][row] = v.y;
                es[lc + 2][row] = v.z; es[lc + 3][row] = v.w;
            }
            __syncthreads();

            #pragma unroll
            for (int d = 0; d < DC; d++) {
                float zr[8], er[8];
                *(float4*)&zr[0] = *(const float4*)&zs[d][r0];
                *(float4*)&zr[4] = *(const float4*)&zs[d][r1];
                *(float4*)&er[0] = *(const float4*)&es[d][c0];
                *(float4*)&er[4] = *(const float4*)&es[d][c1];
                #pragma unroll
                for (int i = 0; i < 8; i++) {
                    #pragma unroll
                    for (int j = 0; j < 8; j++)
                        acc[i][j] = fmaf(zr[i], er[j], acc[i][j]);
                }
            }
            __syncthreads();
        }

        // epilogue: dist = ||e||^2 - 2*dot, running argmin (first-index tie)
        #pragma unroll
        for (int j = 0; j < 8; j++) {
            int code = ct + ((j < 4) ? (c0 + j) : (c1 + j - 4));
            float e2 = g_e2[code];
            #pragma unroll
            for (int i = 0; i < 8; i++) {
                float dist = fmaf(-2.f, acc[i][j], e2);
                if (dist < best[i]) { best[i] = dist; bidx[i] = code; }
            }
        }
    }

    // reduce across the 16 tx lanes (contiguous half-warp groups)
    #pragma unroll
    for (int off = 1; off < 16; off <<= 1) {
        #pragma unroll
        for (int i = 0; i < 8; i++) {
            float ob = __shfl_xor_sync(0xFFFFFFFFu, best[i], off);
            int   oi = __shfl_xor_sync(0xFFFFFFFFu, bidx[i], off);
            if (ob < best[i] || (ob == best[i] && oi < bidx[i])) {
                best[i] = ob; bidx[i] = oi;
            }
        }
    }
    if (tx == 0) {
        #pragma unroll
        for (int i = 0; i < 8; i++) {
            int row = (i < 4) ? (r0 + i) : (r1 + i - 4);
            g_idx[m0 + row] = bidx[i];
        }
    }
}

// ---------------------------------------------------------------------------
// k_out: warp-per-row gather z_q, write z_q_st = z + (z_q - z) exactly as the
// reference does, accumulate commitment-loss partials (deterministic per-block
// reduction), histogram counts, and emit idx as float.
// ---------------------------------------------------------------------------
__global__ void k_out(const float* __restrict__ z, const float* __restrict__ embed,
                      float* __restrict__ out, int N, long long idx_off) {
    const int warp = threadIdx.x >> 5;
    const int lane = threadIdx.x & 31;
    const int row = blockIdx.x * 8 + warp;
    __shared__ double wsum[8];

    double s = 0.0;
    if (row < N) {
        int idx = g_idx[row];
        if (lane == 0) {
            atomicAdd(&g_counts[idx], 1);
            out[idx_off + row] = (float)idx;
        }
        const float4* zp = (const float4*)(z + (size_t)row * DIM);
        const float4* ep = (const float4*)(embed + (size_t)idx * DIM);
        float4* op = (float4*)(out + (size_t)row * DIM);
        #pragma unroll
        for (int q = 0; q < DIM / 4 / 32; q++) {
            int c = lane + q * 32;
            float4 zv = zp[c], ev = ep[c];
            float dx = ev.x - zv.x, dy = ev.y - zv.y;
            float dz2 = ev.z - zv.z, dw = ev.w - zv.w;
            float4 o;
            o.x = zv.x + dx; o.y = zv.y + dy;
            o.z = zv.z + dz2; o.w = zv.w + dw;
            op[c] = o;
            s += (double)dx * dx + (double)dy * dy
               + (double)dz2 * dz2 + (double)dw * dw;
        }
    }
    #pragma unroll
    for (int o = 16; o; o >>= 1) s += __shfl_xor_sync(0xFFFFFFFFu, s, o);
    if (lane == 0) wsum[warp] = s;
    __syncthreads();
    if (threadIdx.x == 0) {
        double t = 0.0;
        #pragma unroll
        for (int w = 0; w < 8; w++) t += wsum[w];
        g_losspart[blockIdx.x] = t;
    }
}

// ---------------------------------------------------------------------------
// k_fin: single block — loss = beta * mean, perplexity from histogram.
// ---------------------------------------------------------------------------
__global__ void k_fin(float* __restrict__ out, int N, int K,
                      long long scalar_off, int nparts) {
    __shared__ double sm[256];
    const int tid = threadIdx.x;

    double s = 0.0;
    for (int i = tid; i < nparts; i += 256) s += g_losspart[i];
    sm[tid] = s;
    __syncthreads();
    for (int o = 128; o; o >>= 1) {
        if (tid < o) sm[tid] += sm[tid + o];
        __syncthreads();
    }
    double loss = 0.25 * sm[0] / ((double)N * (double)DIM);
    __syncthreads();

    double ent = 0.0;
    const double invN = 1.0 / (double)N;
    for (int k = tid; k < K; k += 256) {
        double p = (double)g_counts[k] * invN;
        ent += p * log(p + 1e-12);
    }
    sm[tid] = ent;
    __syncthreads();
    for (int o = 128; o; o >>= 1) {
        if (tid < o) sm[tid] += sm[tid + o];
        __syncthreads();
    }
    if (tid == 0) {
        out[scalar_off]     = (float)loss;
        out[scalar_off + 1] = (float)exp(-sm[0]);
    }
}

// ---------------------------------------------------------------------------
extern "C" void kernel_launch(void* const* d_in, const int* in_sizes, int n_in,
                              void* d_out, int out_size) {
    const float* z     = (const float*)d_in[0];
    const float* embed = (const float*)d_in[1];
    int nz = in_sizes[0], ne = in_sizes[1];
    if (nz < ne) {  // defensive: z is the larger tensor
        const float* t = z; z = embed; embed = t;
        int s = nz; nz = ne; ne = s;
    }
    const int N = nz / DIM;   // 32768
    const int K = ne / DIM;   // 8192
    float* out = (float*)d_out;
    const long long nsd = (long long)N * DIM;

    k_prep  <<<(K + 7) / 8, 256>>>(embed, K);
    k_argmin<<<N / BM, TPB>>>(z, embed, N, K);
    k_out   <<<N / 8, 256>>>(z, embed, out, N, nsd + 2);
    k_fin   <<<1, 256>>>(out, N, K, nsd, N / 8);
}

// round 17
// speedup vs baseline: 1.9012x; 1.9012x over previous
#include <cuda_runtime.h>
#include <math.h>
#include <stdint.h>

// VQ-EMA inference forward. Tensor path = mma.sync.m16n8k8 tf32 (sm_80 PTX,
// NOT 'a'-gated -- tcgen05 is unusable: harness PTX target is plain sm_103).
// Exact fp32 fixup GEMM for rows with small argmin margin.
//   z [32768, 256] fp32, embed [8192, 256] fp32
//   out fp32: z_q_st [N*D] | loss | perplexity | idx-as-float [N]

#define DIM   256
#define BM    128          // z rows per CTA
#define BN    64           // codes per tile
#define TPB   256
#define MAXN  32768
#define MAXK  8192
#define NTILE (MAXK / BN)      // 128 code tiles
#define NIT   (NTILE * 8)      // 1024 chunks (32-d each)
#define TAU   0.25f

#define ASTRIDE 260        // A smem row stride (words), 260%32=4 -> spread banks
#define BSTRIDE 36         // B smem row stride
#define BBUF    (BN * BSTRIDE)

// permute d within groups of 8 so tf32 A-frag regs (q, q+4) sit adjacent
#define PERM(d) (((d) & ~7) | (((d) & 3) << 1) | (((d) >> 2) & 1))

__device__ __align__(16) int    g_idx[MAXN];
__device__ __align__(16) float  g_e2[MAXK];
__device__ __align__(16) int    g_counts[MAXK];
__device__ double g_losspart[MAXN / 8];
__device__ __align__(16) int    g_fixrows[MAXN];
__device__ unsigned long long   g_fix64[MAXN];
__device__ int    g_nfix;

// ---------------------------------------------------------------------------
// helpers
// ---------------------------------------------------------------------------
__device__ __forceinline__ uint32_t smem_u32(const void* p) {
    uint32_t a;
    asm("{ .reg .u64 t; cvta.to.shared.u64 t, %1; cvt.u32.u64 %0, t; }" : "=r"(a) : "l"(p));
    return a;
}
__device__ __forceinline__ void cpa16(const float* dst_smem, const float* src) {
    asm volatile("cp.async.cg.shared.global [%0], [%1], 16;"
                 :: "r"(smem_u32(dst_smem)), "l"(src));
}
#define CPA_COMMIT() asm volatile("cp.async.commit_group;" ::: "memory")
#define CPA_WAIT(n)  asm volatile("cp.async.wait_group %0;" :: "n"(n) : "memory")

__device__ __forceinline__ uint32_t f2tf32(float x) {
    uint32_t r; asm("cvt.rna.tf32.f32 %0, %1;" : "=r"(r) : "f"(x)); return r;
}
__device__ __forceinline__ void mma_tf32(float* c, const uint32_t* a,
                                         uint32_t b0, uint32_t b1) {
    asm("mma.sync.aligned.m16n8k8.row.col.f32.tf32.tf32.f32 "
        "{%0,%1,%2,%3}, {%4,%5,%6,%7}, {%8,%9}, {%0,%1,%2,%3};"
        : "+f"(c[0]), "+f"(c[1]), "+f"(c[2]), "+f"(c[3])
        : "r"(a[0]), "r"(a[1]), "r"(a[2]), "r"(a[3]), "r"(b0), "r"(b1));
}
__device__ __forceinline__ unsigned long long packdi(float d, int c) {
    unsigned u = __float_as_uint(d);
    u = (u & 0x80000000u) ? ~u : (u | 0x80000000u);
    return ((unsigned long long)u << 32) | (unsigned)c;
}

// ---------------------------------------------------------------------------
// k_prep: ||e_k||^2, zero histogram + fixup counter
// ---------------------------------------------------------------------------
__global__ void k_prep(const float* __restrict__ embed, int K) {
    int code = blockIdx.x * 8 + (threadIdx.x >> 5);
    int lane = threadIdx.x & 31;
    if (blockIdx.x == 0 && threadIdx.x == 0) g_nfix = 0;
    if (code < K) {
        const float* e = embed + (size_t)code * DIM;
        float s = 0.f;
        #pragma unroll
        for (int q = 0; q < DIM / 32; q++) { float v = e[lane + q * 32]; s = fmaf(v, v, s); }
        #pragma unroll
        for (int o = 16; o; o >>= 1) s += __shfl_xor_sync(0xFFFFFFFFu, s, o);
        if (lane == 0) { g_e2[code] = s; g_counts[code] = 0; }
    }
}

// ---------------------------------------------------------------------------
// k_main: tf32 mma.sync GEMM-argmin. A resident (tf32-rounded, frag-permuted),
// B double-buffered 64x32 chunks via cp.async.
// smem floats: As[128*260] | Bs[2*64*36] | e2s[2*64] | mb[256] mb2[256] mix[256]
// ---------------------------------------------------------------------------
#define OFF_B   (BM * ASTRIDE)
#define OFF_E2  (OFF_B + 2 * BBUF)
#define OFF_MB  (OFF_E2 + 2 * BN)
#define OFF_MB2 (OFF_MB + 256)
#define OFF_MIX (OFF_MB2 + 256)
#define SM_WORDS (OFF_MIX + 256)

__device__ __forceinline__ void load_chunk(float* smf, const float* __restrict__ embed,
                                           int it, int tid) {
    int t = it >> 3, dc = it & 7, buf = it & 1;
    float* bdst = smf + OFF_B + buf * BBUF;
    const float* bsrc = embed + (size_t)t * BN * DIM + dc * 32;
    #pragma unroll
    for (int p = 0; p < 2; p++) {
        int idx = p * TPB + tid;          // 0..511 float4s
        int code = idx >> 3, fg = idx & 7;
        cpa16(bdst + code * BSTRIDE + fg * 4, bsrc + (size_t)code * DIM + fg * 4);
    }
    if (dc == 0 && tid < 16)
        cpa16(smf + OFF_E2 + (t & 1) * BN + tid * 4, &g_e2[t * BN + tid * 4]);
}

__global__ void __launch_bounds__(TPB, 1)
k_main(const float* __restrict__ z, const float* __restrict__ embed) {
    extern __shared__ float smf[];
    const int tid = threadIdx.x;
    const int wid = tid >> 5, lane = tid & 31;
    const int g = lane >> 2, q = lane & 3;
    const int wm = (wid & 3) * 32;        // warp row base
    const int wn = (wid >> 2) * 32;       // warp col base within BN
    const int m0 = blockIdx.x * BM;

    // A prologue: load z rows, round to tf32, store permuted
    #pragma unroll
    for (int i = 0; i < 32; i++) {
        int idx = i * TPB + tid;          // 8192 float4s
        int row = idx >> 6, f4 = idx & 63, d = f4 * 4;
        float4 v = *(const float4*)(z + (size_t)(m0 + row) * DIM + d);
        float* ap = smf + row * ASTRIDE;
        ap[PERM(d + 0)] = __uint_as_float(f2tf32(v.x));
        ap[PERM(d + 1)] = __uint_as_float(f2tf32(v.y));
        ap[PERM(d + 2)] = __uint_as_float(f2tf32(v.z));
        ap[PERM(d + 3)] = __uint_as_float(f2tf32(v.w));
    }
    load_chunk(smf, embed, 0, tid); CPA_COMMIT();
    load_chunk(smf, embed, 1, tid); CPA_COMMIT();
    CPA_WAIT(1);
    __syncthreads();

    float best[4], best2[4]; int bidx[4];
    #pragma unroll
    for (int s = 0; s < 4; s++) { best[s] = INFINITY; best2[s] = INFINITY; bidx[s] = 0; }

    float acc[2][4][4];

    for (int it = 0; it < NIT; it++) {
        const int ct = it >> 3, dc = it & 7, buf = it & 1;
        if (dc == 0) {
            #pragma unroll
            for (int i = 0; i < 2; i++)
                #pragma unroll
                for (int j = 0; j < 4; j++)
                    #pragma unroll
                    for (int r = 0; r < 4; r++) acc[i][j][r] = 0.f;
        }
        const float* bsub = smf + OFF_B + buf * BBUF + wn * BSTRIDE;

        #pragma unroll
        for (int ks = 0; ks < 4; ks++) {
            const int k0 = dc * 32 + ks * 8;   // A k-base (perm keeps 8-groups)
            const int kb = ks * 8;             // B within-chunk k-base
            uint32_t a[2][4];
            #pragma unroll
            for (int i = 0; i < 2; i++) {
                const float* ap = smf + (wm + i * 16 + g) * ASTRIDE + k0 + 2 * q;
                float2 lo = *(const float2*)ap;                   // (a0,a2)
                float2 hi = *(const float2*)(ap + 8 * ASTRIDE);   // (a1,a3)
                a[i][0] = __float_as_uint(lo.x); a[i][1] = __float_as_uint(hi.x);
                a[i][2] = __float_as_uint(lo.y); a[i][3] = __float_as_uint(hi.y);
            }
            #pragma unroll
            for (int j = 0; j < 4; j++) {
                const float* bp = bsub + (j * 8 + g) * BSTRIDE + kb + q;
                uint32_t b0 = f2tf32(bp[0]);
                uint32_t b1 = f2tf32(bp[4]);
                mma_tf32(acc[0][j], a[0], b0, b1);
                mma_tf32(acc[1][j], a[1], b0, b1);
            }
        }

        if (dc == 7) {
            const float* e2p = smf + OFF_E2 + (ct & 1) * BN + wn;
            #pragma unroll
            for (int j = 0; j < 4; j++) {
                float e20 = e2p[j * 8 + 2 * q];
                float e21 = e2p[j * 8 + 2 * q + 1];
                int c0 = ct * BN + wn + j * 8 + 2 * q;
                #pragma unroll
                for (int i = 0; i < 2; i++) {
                    float d00 = fmaf(-2.f, acc[i][j][0], e20);
                    float d01 = fmaf(-2.f, acc[i][j][1], e21);
                    float d10 = fmaf(-2.f, acc[i][j][2], e20);
                    float d11 = fmaf(-2.f, acc[i][j][3], e21);
                    int s0 = i * 2, s1 = i * 2 + 1;
                    if (d00 < best[s0]) { best2[s0] = best[s0]; best[s0] = d00; bidx[s0] = c0; }
                    else if (d00 < best2[s0]) best2[s0] = d00;
                    if (d01 < best[s0]) { best2[s0] = best[s0]; best[s0] = d01; bidx[s0] = c0 + 1; }
                    else if (d01 < best2[s0]) best2[s0] = d01;
                    if (d10 < best[s1]) { best2[s1] = best[s1]; best[s1] = d10; bidx[s1] = c0; }
                    else if (d10 < best2[s1]) best2[s1] = d10;
                    if (d11 < best[s1]) { best2[s1] = best[s1]; best[s1] = d11; bidx[s1] = c0 + 1; }
                    else if (d11 < best2[s1]) best2[s1] = d11;
                }
            }
        }

        __syncthreads();                       // everyone done reading buf
        if (it + 2 < NIT) {
            load_chunk(smf, embed, it + 2, tid); CPA_COMMIT();
            CPA_WAIT(1);                       // chunk it+1 resident
        } else {
            CPA_WAIT(0);
        }
        __syncthreads();
    }

    // merge the 4 q-lanes holding the same rows (cols were split across q)
    #pragma unroll
    for (int off = 1; off <= 2; off <<= 1) {
        #pragma unroll
        for (int s = 0; s < 4; s++) {
            float ob  = __shfl_xor_sync(0xFFFFFFFFu, best[s], off);
            float ob2 = __shfl_xor_sync(0xFFFFFFFFu, best2[s], off);
            int   oi  = __shfl_xor_sync(0xFFFFFFFFu, bidx[s], off);
            if (ob < best[s] || (ob == best[s] && oi < bidx[s])) {
                best2[s] = fminf(ob2, best[s]); best[s] = ob; bidx[s] = oi;
            } else {
                best2[s] = fminf(best2[s], ob);
            }
        }
    }
    float* mb  = smf + OFF_MB;
    float* mb2 = smf + OFF_MB2;
    int*   mix = (int*)(smf + OFF_MIX);
    if (q == 0) {
        int half = wid >> 2;
        #pragma unroll
        for (int s = 0; s < 4; s++) {
            int row = wm + (s >> 1) * 16 + (s & 1) * 8 + g;
            mb[row * 2 + half]  = best[s];
            mb2[row * 2 + half] = best2[s];
            mix[row * 2 + half] = bidx[s];
        }
    }
    __syncthreads();
    if (tid < BM) {
        float b0 = mb[tid * 2], b1 = mb[tid * 2 + 1];
        float s0 = mb2[tid * 2], s1 = mb2[tid * 2 + 1];
        int   i0 = mix[tid * 2], i1 = mix[tid * 2 + 1];
        float fb, fs; int fi;
        if (b1 < b0 || (b1 == b0 && i1 < i0)) { fb = b1; fi = i1; fs = fminf(s1, b0); }
        else                                  { fb = b0; fi = i0; fs = fminf(s0, b1); }
        g_idx[m0 + tid] = fi;
        if (fs - fb < TAU) {
            int p = atomicAdd(&g_nfix, 1);
            g_fixrows[p] = m0 + tid;
            g_fix64[p] = 0xFFFFFFFFFFFFFFFFull;
        }
    }
}

// ---------------------------------------------------------------------------
// k_fixup2: exact fp32 GEMM-argmin over flagged rows. Work item =
// (128-row tile) x (256-code slice); packed atomicMin merge.
// ---------------------------------------------------------------------------
__global__ void __launch_bounds__(256, 2)
k_fixup2(const float* __restrict__ z, const float* __restrict__ embed) {
    __shared__ float zs[32][132];
    __shared__ float es[32][132];
    __shared__ int rid[128];
    const int F = g_nfix;
    if (F == 0) return;
    const int ntile = (F + 127) >> 7;
    const int items = ntile * 32;

    const int tid = threadIdx.x;
    const int tx = tid & 15, ty = tid >> 4;
    const int lr = tid >> 3, lc = (tid & 7) * 4;

    for (int item = blockIdx.x; item < items; item += gridDim.x) {
        const int rt = item >> 5, ksl = item & 31;
        __syncthreads();
        if (tid < 128) {
            int p = rt * 128 + tid;
            rid[tid] = g_fixrows[p < F ? p : F - 1];
        }
        __syncthreads();

        float bst[8]; int bix[8];
        #pragma unroll
        for (int i = 0; i < 8; i++) { bst[i] = INFINITY; bix[i] = 0; }

        for (int ct = ksl * 256; ct < ksl * 256 + 256; ct += 128) {
            float acc[8][8];
            #pragma unroll
            for (int i = 0; i < 8; i++)
                #pragma unroll
                for (int j = 0; j < 8; j++) acc[i][j] = 0.f;

            for (int dc = 0; dc < DIM; dc += 32) {
                #pragma unroll
                for (int p = 0; p < 4; p++) {
                    int row = lr + p * 32;
                    float4 v = *(const float4*)(z + (size_t)rid[row] * DIM + dc + lc);
                    zs[lc + 0][row] = v.x; zs[lc + 1][row] = v.y;
                    zs[lc + 2][row] = v.z; zs[lc + 3][row] = v.w;
                }
                #pragma unroll
                for (int p = 0; p < 4; p++) {
                    int row = lr + p * 32;
                    float4 v = *(const float4*)(embed + (size_t)(ct + row) * DIM + dc + lc);
                    es[lc + 0][row] = v.x; es[lc + 1][row] = v.y;
                    es[lc + 2][row] = v.z; es[lc + 3][row] = v.w;
                }
                __syncthreads();
                #pragma unroll
                for (int d = 0; d < 32; d++) {
                    float zr[8], er[8];
                    *(float4*)&zr[0] = *(const float4*)&zs[d][ty * 4];
                    *(float4*)&zr[4] = *(const float4*)&zs[d][64 + ty * 4];
                    *(float4*)&er[0] = *(const float4*)&es[d][tx * 4];
                    *(float4*)&er[4] = *(const float4*)&es[d][64 + tx * 4];
                    #pragma unroll
                    for (int i = 0; i < 8; i++)
                        #pragma unroll
                        for (int j = 0; j < 8; j++)
                            acc[i][j] = fmaf(zr[i], er[j], acc[i][j]);
                }
                __syncthreads();
            }
            #pragma unroll
            for (int j = 0; j < 8; j++) {
                int code = ct + ((j < 4) ? (tx * 4 + j) : (64 + tx * 4 + j - 4));
                float e2 = g_e2[code];
                #pragma unroll
                for (int i = 0; i < 8; i++) {
                    float dist = fmaf(-2.f, acc[i][j], e2);
                    if (dist < bst[i]) { bst[i] = dist; bix[i] = code; }
                }
            }
        }
        #pragma unroll
        for (int off = 1; off < 16; off <<= 1) {
            #pragma unroll
            for (int i = 0; i < 8; i++) {
                float ob = __shfl_xor_sync(0xFFFFFFFFu, bst[i], off);
                int   oi = __shfl_xor_sync(0xFFFFFFFFu, bix[i], off);
                if (ob < bst[i] || (ob == bst[i] && oi < bix[i])) { bst[i] = ob; bix[i] = oi; }
            }
        }
        if (tx == 0) {
            #pragma unroll
            for (int i = 0; i < 8; i++) {
                int rowl = (i < 4) ? (ty * 4 + i) : (64 + ty * 4 + i - 4);
                int p = rt * 128 + rowl;
                if (p < F) atomicMin(&g_fix64[p], packdi(bst[i], bix[i]));
            }
        }
    }
}

__global__ void k_apply() {
    const int F = g_nfix;
    for (int p = blockIdx.x * blockDim.x + threadIdx.x; p < F; p += gridDim.x * blockDim.x)
        g_idx[g_fixrows[p]] = (int)(g_fix64[p] & 0xFFFFFFFFu);
}

// ---------------------------------------------------------------------------
// k_out: gather z_q, straight-through output, loss partials, histogram, idx
// ---------------------------------------------------------------------------
__global__ void k_out(const float* __restrict__ z, const float* __restrict__ embed,
                      float* __restrict__ out, int N, long long idx_off) {
    const int warp = threadIdx.x >> 5;
    const int lane = threadIdx.x & 31;
    const int row = blockIdx.x * 8 + warp;
    __shared__ double wsum[8];

    double s = 0.0;
    if (row < N) {
        int idx = g_idx[row];
        if (lane == 0) {
            atomicAdd(&g_counts[idx], 1);
            out[idx_off + row] = (float)idx;
        }
        const float4* zp = (const float4*)(z + (size_t)row * DIM);
        const float4* ep = (const float4*)(embed + (size_t)idx * DIM);
        float4* op = (float4*)(out + (size_t)row * DIM);
        #pragma unroll
        for (int q = 0; q < DIM / 4 / 32; q++) {
            int c = lane + q * 32;
            float4 zv = zp[c], ev = ep[c];
            float dx = ev.x - zv.x, dy = ev.y - zv.y;
            float dz2 = ev.z - zv.z, dw = ev.w - zv.w;
            float4 o;
            o.x = zv.x + dx; o.y = zv.y + dy; o.z = zv.z + dz2; o.w = zv.w + dw;
            op[c] = o;
            s += (double)dx * dx + (double)dy * dy + (double)dz2 * dz2 + (double)dw * dw;
        }
    }
    #pragma unroll
    for (int o = 16; o; o >>= 1) s += __shfl_xor_sync(0xFFFFFFFFu, s, o);
    if (lane == 0) wsum[warp] = s;
    __syncthreads();
    if (threadIdx.x == 0) {
        double t = 0.0;
        #pragma unroll
        for (int w = 0; w < 8; w++) t += wsum[w];
        g_losspart[blockIdx.x] = t;
    }
}

// ---------------------------------------------------------------------------
// k_fin: loss + perplexity
// ---------------------------------------------------------------------------
__global__ void k_fin(float* __restrict__ out, int N, int K,
                      long long scalar_off, int nparts) {
    __shared__ double sm[256];
    const int tid = threadIdx.x;

    double s = 0.0;
    for (int i = tid; i < nparts; i += 256) s += g_losspart[i];
    sm[tid] = s;
    __syncthreads();
    for (int o = 128; o; o >>= 1) { if (tid < o) sm[tid] += sm[tid + o]; __syncthreads(); }
    double loss = 0.25 * sm[0] / ((double)N * (double)DIM);
    __syncthreads();

    float ent = 0.f;
    const float invN = 1.0f / (float)N;
    for (int k = tid; k < K; k += 256) {
        float p = (float)g_counts[k] * invN;
        ent += p * logf(p + 1e-12f);
    }
    sm[tid] = (double)ent;
    __syncthreads();
    for (int o = 128; o; o >>= 1) { if (tid < o) sm[tid] += sm[tid + o]; __syncthreads(); }
    if (tid == 0) {
        out[scalar_off]     = (float)loss;
        out[scalar_off + 1] = expf(-(float)sm[0]);
    }
}

// ---------------------------------------------------------------------------
extern "C" void kernel_launch(void* const* d_in, const int* in_sizes, int n_in,
                              void* d_out, int out_size) {
    const float* z     = (const float*)d_in[0];
    const float* embed = (const float*)d_in[1];
    int nz = in_sizes[0], ne = in_sizes[1];
    if (nz < ne) {
        const float* t = z; z = embed; embed = t;
        int s = nz; nz = ne; ne = s;
    }
    const int N = nz / DIM;   // 32768
    const int K = ne / DIM;   // 8192
    float* out = (float*)d_out;
    const long long nsd = (long long)N * DIM;
    const int smbytes = SM_WORDS * 4;

    cudaFuncSetAttribute(k_main, cudaFuncAttributeMaxDynamicSharedMemorySize, smbytes);

    k_prep   <<<(K + 7) / 8, 256>>>(embed, K);
    k_main   <<<N / BM, TPB, smbytes>>>(z, embed);
    k_fixup2 <<<256, 256>>>(z, embed);
    k_apply  <<<32, 256>>>();
    k_out    <<<N / 8, 256>>>(z, embed, out, N, nsd + 2);
    k_fin    <<<1, 256>>>(out, N, K, nsd, N / 8);
}